// round 12
// baseline (speedup 1.0000x reference)
#include <cuda_runtime.h>
#include <cuda_bf16.h>
#include <math.h>
#include <stdint.h>

// ---------------- problem constants ----------------
#define NB   8
#define NN   4096          // H*W
#define CVD  256
#define CTD  512
#define NT   77
#define TPAD 96
#define NHH  8
#define DH   32
#define TOPM 5
#define ROWS (NB*NN)       // 32768
#define TB   8             // tokens per kv block

// ---------------- scratch (device globals; no allocs allowed) ----------------
__device__ float g_x[ROWS*CVD];          // LN1 output
__device__ float g_q[ROWS*CVD];          // q projection (l2-normed in epilogue)
__device__ float g_kT[NB*NHH*DH*TPAD];   // k transposed [b][h][d][t]
__device__ float g_v[NB*NT*CVD];         // v
__device__ int   g_pad[NB*NT];           // pad flags
__device__ float g_aligned[ROWS*CVD];    // attention output
__device__ float g_proj[ROWS*CVD];       // aligned @ Wo + bo
__device__ float g_y2[ROWS*CVD];         // LN2 output
__device__ float g_hdn[ROWS*4*CVD];      // FFN hidden (gelu)

// ---------------- LN1 ----------------
__global__ __launch_bounds__(256) void ln1_kernel(const float* __restrict__ in,
                                                  const float* __restrict__ g,
                                                  const float* __restrict__ b) {
    int warp = (blockIdx.x * blockDim.x + threadIdx.x) >> 5;
    int lane = threadIdx.x & 31;
    const float* row = in + (size_t)warp * CVD;
    float v[8]; float s = 0.f, ss = 0.f;
#pragma unroll
    for (int i = 0; i < 8; i++) { v[i] = row[lane*8 + i]; s += v[i]; ss += v[i]*v[i]; }
#pragma unroll
    for (int o = 16; o; o >>= 1) { s += __shfl_xor_sync(~0u, s, o); ss += __shfl_xor_sync(~0u, ss, o); }
    float mu  = s * (1.f/CVD);
    float var = ss * (1.f/CVD) - mu*mu;
    float inv = rsqrtf(var + 1e-5f);
    float* orow = g_x + (size_t)warp * CVD;
#pragma unroll
    for (int i = 0; i < 8; i++) { int c = lane*8 + i; orow[c] = (v[i]-mu)*inv*g[c] + b[c]; }
}

// ---------------- LN2 + residual ----------------
__global__ __launch_bounds__(256) void ln2res_kernel(const float* __restrict__ g,
                                                     const float* __restrict__ b,
                                                     const float* __restrict__ alpha_p) {
    int warp = (blockIdx.x * blockDim.x + threadIdx.x) >> 5;
    int lane = threadIdx.x & 31;
    float alpha = alpha_p[0];
    const float* xr = g_x    + (size_t)warp * CVD;
    const float* pr = g_proj + (size_t)warp * CVD;
    float v[8]; float s = 0.f, ss = 0.f;
#pragma unroll
    for (int i = 0; i < 8; i++) {
        int c = lane*8 + i;
        v[i] = xr[c] + alpha * pr[c];
        s += v[i]; ss += v[i]*v[i];
    }
#pragma unroll
    for (int o = 16; o; o >>= 1) { s += __shfl_xor_sync(~0u, s, o); ss += __shfl_xor_sync(~0u, ss, o); }
    float mu  = s * (1.f/CVD);
    float var = ss * (1.f/CVD) - mu*mu;
    float inv = rsqrtf(var + 1e-5f);
    float* orow = g_y2 + (size_t)warp * CVD;
#pragma unroll
    for (int i = 0; i < 8; i++) { int c = lane*8 + i; orow[c] = (v[i]-mu)*inv*g[c] + b[c]; }
}

// ---------------- K/V projection, 8 tokens per block (weight reuse in L1/regs) ----------------
__global__ __launch_bounds__(256) void kv_kernel(const float* __restrict__ text,
                                                 const float* __restrict__ Wk, const float* __restrict__ bk,
                                                 const float* __restrict__ Wv, const float* __restrict__ bv) {
    int bt0 = blockIdx.x * TB;
    int c   = threadIdx.x;
    int wid = c >> 5, lane = c & 31;
    __shared__ float txt[TB][CTD];

    for (int i = c; i < TB*CTD; i += 256) {
        int j = i >> 9, kk = i & 511;
        txt[j][kk] = text[(size_t)(bt0 + j) * CTD + kk];
    }
    __syncthreads();

    // pad flag: warp wid handles row wid (exact for all-zero pad rows)
    {
        float sum = 0.f;
        for (int kk = lane; kk < CTD; kk += 32) sum += fabsf(txt[wid][kk]);
#pragma unroll
        for (int o = 16; o; o >>= 1) sum += __shfl_xor_sync(~0u, sum, o);
        if (lane == 0) g_pad[bt0 + wid] = (sum <= 1e-6f);
    }

    float ak[TB], av_[TB];
#pragma unroll
    for (int j = 0; j < TB; j++) { ak[j] = bk[c]; av_[j] = bv[c]; }

#pragma unroll 2
    for (int kk = 0; kk < CTD; kk++) {
        float wk = Wk[kk*CVD + c];
        float wv = Wv[kk*CVD + c];
#pragma unroll
        for (int j = 0; j < TB; j++) {
            float tv = txt[j][kk];
            ak[j]  += tv * wk;
            av_[j] += tv * wv;
        }
    }

    int h = c >> 5, d = c & 31;
#pragma unroll
    for (int j = 0; j < TB; j++) {
        int bt = bt0 + j;
        int b = bt / NT, t = bt - b * NT;
        float kc = ak[j];
        float ss = kc * kc;
#pragma unroll
        for (int o = 16; o; o >>= 1) ss += __shfl_xor_sync(~0u, ss, o);
        kc /= fmaxf(sqrtf(ss), 1e-6f);
        g_kT[((b*NHH + h)*DH + d)*TPAD + t] = kc;
        g_v[(size_t)bt*CVD + c] = av_[j];
    }
}

// ---------------- order-preserving float<->uint ----------------
__device__ __forceinline__ uint32_t ford(float f) {
    uint32_t u = __float_as_uint(f);
    return (u & 0x80000000u) ? ~u : (u | 0x80000000u);
}
__device__ __forceinline__ float finv(uint32_t m) {
    uint32_t u = (m & 0x80000000u) ? (m ^ 0x80000000u) : ~m;
    return __uint_as_float(u);
}

// ---------------- attention: 2 rows per block, warp per head; redux top-5 ----------------
__global__ __launch_bounds__(256) void attn_kernel(const float* __restrict__ logit_scale) {
    int row0 = blockIdx.x * 2;
    int b    = row0 >> 12;
    int tid  = threadIdx.x;
    int h = tid >> 5, lane = tid & 31;
    __shared__ float qs[2][CVD];
    __shared__ int   spad[NT];
    qs[0][tid] = g_q[(size_t)row0 * CVD + tid];
    qs[1][tid] = g_q[(size_t)(row0 + 1) * CVD + tid];
    if (tid < NT) spad[tid] = g_pad[b*NT + tid];
    __syncthreads();

    float ls = logit_scale[0];
    float scale = expf(fminf(fmaxf(ls, -2.f), 2.f)) * 0.17677669529663687f;

    const float* kT = g_kT + ((size_t)(b*NHH + h) * DH) * TPAD;  // [d][t]
    float acc[2][3] = {};
#pragma unroll
    for (int d = 0; d < DH; d++) {
        const float* kr = kT + d*TPAD;
        float k0 = kr[lane], k1 = kr[lane + 32], k2 = kr[lane + 64];
        float q0 = qs[0][h*DH + d];
        float q1 = qs[1][h*DH + d];
        acc[0][0] += q0 * k0; acc[0][1] += q0 * k1; acc[0][2] += q0 * k2;
        acc[1][0] += q1 * k0; acc[1][1] += q1 * k1; acc[1][2] += q1 * k2;
    }

    bool p0 = spad[lane];
    bool p1 = (lane + 32 >= NT) || spad[lane + 32];
    bool p2 = (lane + 64 >= NT) || spad[lane + 64];

#pragma unroll
    for (int rr = 0; rr < 2; rr++) {
        float s0 = !p0 ? acc[rr][0] * scale : -INFINITY;
        float s1 = !p1 ? acc[rr][1] * scale : -INFINITY;
        float s2 = !p2 ? acc[rr][2] * scale : -INFINITY;

        uint32_t o0 = ford(s0), o1 = ford(s1), o2 = ford(s2);

        float topv[TOPM]; int topt[TOPM];
#pragma unroll
        for (int it = 0; it < TOPM; it++) {
            uint32_t loc = o0 > o1 ? o0 : o1;
            if (o2 > loc) loc = o2;
            uint32_t m = __reduce_max_sync(0xffffffffu, loc);
            topv[it] = finv(m);
            int t;
            unsigned b0 = __ballot_sync(0xffffffffu, o0 == m);
            if (b0) t = __ffs(b0) - 1;
            else {
                unsigned b1 = __ballot_sync(0xffffffffu, o1 == m);
                if (b1) t = 32 + __ffs(b1) - 1;
                else {
                    unsigned b2 = __ballot_sync(0xffffffffu, o2 == m);
                    t = 64 + __ffs(b2) - 1;
                }
            }
            topt[it] = t;
            if ((t & 31) == lane) {
                if (t < 32) o0 = 0u; else if (t < 64) o1 = 0u; else o2 = 0u;
            }
        }

        float outv = 0.f;
        float mx = topv[0];
        if (!(mx == -INFINITY)) {
            float e[TOPM]; float ws = 0.f;
#pragma unroll
            for (int i = 0; i < TOPM; i++) { e[i] = expf(topv[i] - mx); ws += e[i]; }
            float inv = 1.f / ws;
            const float* vb = g_v + (size_t)b * NT * CVD + h * DH + lane;
#pragma unroll
            for (int i = 0; i < TOPM; i++) outv += (e[i] * inv) * vb[(size_t)topt[i] * CVD];
        }
        g_aligned[(size_t)(row0 + rr) * CVD + h*DH + lane] = outv;
    }
}

// ---------------- bf16 split helpers ----------------
__device__ __forceinline__ void bf16_split_pack(float x0, float x1, uint32_t& hi, uint32_t& lo) {
    __nv_bfloat16 h0 = __float2bfloat16_rn(x0);
    __nv_bfloat16 h1 = __float2bfloat16_rn(x1);
    __nv_bfloat16 l0 = __float2bfloat16_rn(x0 - __bfloat162float(h0));
    __nv_bfloat16 l1 = __float2bfloat16_rn(x1 - __bfloat162float(h1));
    hi = (uint32_t)__bfloat16_as_ushort(h0) | ((uint32_t)__bfloat16_as_ushort(h1) << 16);
    lo = (uint32_t)__bfloat16_as_ushort(l0) | ((uint32_t)__bfloat16_as_ushort(l1) << 16);
}
__device__ __forceinline__ void mma16(float* c, const uint32_t* a, const uint32_t* b) {
    asm volatile("mma.sync.aligned.m16n8k16.row.col.f32.bf16.bf16.f32 "
        "{%0,%1,%2,%3}, {%4,%5,%6,%7}, {%8,%9}, {%0,%1,%2,%3};"
        : "+f"(c[0]), "+f"(c[1]), "+f"(c[2]), "+f"(c[3])
        : "r"(a[0]), "r"(a[1]), "r"(a[2]), "r"(a[3]), "r"(b[0]), "r"(b[1]));
}
__device__ __forceinline__ void ldsm4(uint32_t* r, uint32_t saddr) {
    asm volatile("ldmatrix.sync.aligned.m8n8.x4.shared.b16 {%0,%1,%2,%3}, [%4];"
        : "=r"(r[0]), "=r"(r[1]), "=r"(r[2]), "=r"(r[3]) : "r"(saddr));
}

// ---------------- split-bf16 GEMM, A fragments via ldmatrix (unchanged from R10) ----------------
#define ASTRIDE 12
__global__ __launch_bounds__(256) void gemm_bf16s_kernel(const float* __restrict__ A,
                                                         const float* __restrict__ B,
                                                         const float* __restrict__ bias,
                                                         const float* __restrict__ res,
                                                         float* __restrict__ C,
                                                         int M, int N, int K, int mode) {
    __shared__ uint32_t AhS[2][128*ASTRIDE], AlS[2][128*ASTRIDE];
    __shared__ uint32_t Bh[2][8][72],  Bl[2][8][72];

    int tid  = threadIdx.x;
    int lane = tid & 31, wid = tid >> 5;
    int warpM = wid & 3, warpN = wid >> 2;
    int g = lane >> 2, t4 = lane & 3;
    int m0 = blockIdx.y * 128, n0 = blockIdx.x * 64;
    int mbase = warpM * 32, nbase = warpN * 32;

    float c[2][4][4];
#pragma unroll
    for (int i = 0; i < 2; i++)
#pragma unroll
        for (int j = 0; j < 4; j++)
#pragma unroll
            for (int l = 0; l < 4; l++) c[i][j][l] = 0.f;

    int ar   = tid >> 1;
    int ha   = tid & 1;
    int aoff = ar * ASTRIDE + ha * 4;
    int bn   = tid & 63;
    int k2b  = (tid >> 6) * 2;
    const float* Aptr = A + (size_t)(m0 + ar) * K + 8*ha;
    const float* Bptr = B + (size_t)(2*k2b) * N + n0 + bn;

    int lrow = lane & 15;
    int lkof = (lane >> 4) * 4;

    float4 av0, av1;
    float  b00, b01, b10, b11;
    av0 = *(const float4*)(Aptr);
    av1 = *(const float4*)(Aptr + 4);
    b00 = Bptr[0]; b01 = Bptr[N]; b10 = Bptr[2*N]; b11 = Bptr[3*N];

    {
        uint32_t h0,l0,h1,l1,h2,l2,h3,l3;
        bf16_split_pack(av0.x, av0.y, h0, l0);
        bf16_split_pack(av0.z, av0.w, h1, l1);
        bf16_split_pack(av1.x, av1.y, h2, l2);
        bf16_split_pack(av1.z, av1.w, h3, l3);
        *(uint4*)&AhS[0][aoff] = make_uint4(h0, h1, h2, h3);
        *(uint4*)&AlS[0][aoff] = make_uint4(l0, l1, l2, l3);
        uint32_t h, l;
        bf16_split_pack(b00, b01, h, l); Bh[0][k2b  ][bn] = h; Bl[0][k2b  ][bn] = l;
        bf16_split_pack(b10, b11, h, l); Bh[0][k2b+1][bn] = h; Bl[0][k2b+1][bn] = l;
    }

    int stage = 0;
    for (int k0 = 0; k0 < K; k0 += 16) {
        __syncthreads();
        bool more = (k0 + 16) < K;
        if (more) {
            av0 = *(const float4*)(Aptr + k0 + 16);
            av1 = *(const float4*)(Aptr + k0 + 20);
            const float* bp = Bptr + (size_t)(k0 + 16) * N;
            b00 = bp[0]; b01 = bp[N]; b10 = bp[2*N]; b11 = bp[3*N];
        }

        uint32_t ah[2][4], al[2][4], bh[4][2], blo[4][2];
#pragma unroll
        for (int mt = 0; mt < 2; mt++) {
            int r = mbase + mt*16 + lrow;
            uint32_t addrH = (uint32_t)__cvta_generic_to_shared(&AhS[stage][r*ASTRIDE + lkof]);
            uint32_t addrL = (uint32_t)__cvta_generic_to_shared(&AlS[stage][r*ASTRIDE + lkof]);
            ldsm4(ah[mt], addrH);
            ldsm4(al[mt], addrL);
        }
#pragma unroll
        for (int nt = 0; nt < 4; nt++) {
            int cn = nbase + nt*8 + g;
            bh[nt][0]  = Bh[stage][t4][cn];    bh[nt][1]  = Bh[stage][t4+4][cn];
            blo[nt][0] = Bl[stage][t4][cn];    blo[nt][1] = Bl[stage][t4+4][cn];
        }
#pragma unroll
        for (int mt = 0; mt < 2; mt++)
#pragma unroll
            for (int nt = 0; nt < 4; nt++) {
                mma16(c[mt][nt], al[mt], bh[nt]);
                mma16(c[mt][nt], ah[mt], blo[nt]);
                mma16(c[mt][nt], ah[mt], bh[nt]);
            }

        if (more) {
            int ns = stage ^ 1;
            uint32_t h0,l0,h1,l1,h2,l2,h3,l3;
            bf16_split_pack(av0.x, av0.y, h0, l0);
            bf16_split_pack(av0.z, av0.w, h1, l1);
            bf16_split_pack(av1.x, av1.y, h2, l2);
            bf16_split_pack(av1.z, av1.w, h3, l3);
            *(uint4*)&AhS[ns][aoff] = make_uint4(h0, h1, h2, h3);
            *(uint4*)&AlS[ns][aoff] = make_uint4(l0, l1, l2, l3);
            uint32_t h, l;
            bf16_split_pack(b00, b01, h, l); Bh[ns][k2b  ][bn] = h; Bl[ns][k2b  ][bn] = l;
            bf16_split_pack(b10, b11, h, l); Bh[ns][k2b+1][bn] = h; Bl[ns][k2b+1][bn] = l;
        }
        stage ^= 1;
    }

#pragma unroll
    for (int mt = 0; mt < 2; mt++)
#pragma unroll
        for (int nt = 0; nt < 4; nt++) {
            int col = n0 + nbase + nt*8 + t4*2;
            float b0v = bias[col], b1v = bias[col + 1];
            c[mt][nt][0] += b0v; c[mt][nt][1] += b1v;
            c[mt][nt][2] += b0v; c[mt][nt][3] += b1v;
        }

    if (mode == 2) {
#pragma unroll
        for (int mt = 0; mt < 2; mt++) {
            float ss0 = 0.f, ss1 = 0.f;
#pragma unroll
            for (int nt = 0; nt < 4; nt++) {
                ss0 += c[mt][nt][0]*c[mt][nt][0] + c[mt][nt][1]*c[mt][nt][1];
                ss1 += c[mt][nt][2]*c[mt][nt][2] + c[mt][nt][3]*c[mt][nt][3];
            }
            ss0 += __shfl_xor_sync(~0u, ss0, 1); ss0 += __shfl_xor_sync(~0u, ss0, 2);
            ss1 += __shfl_xor_sync(~0u, ss1, 1); ss1 += __shfl_xor_sync(~0u, ss1, 2);
            float i0 = 1.f / fmaxf(sqrtf(ss0), 1e-6f);
            float i1 = 1.f / fmaxf(sqrtf(ss1), 1e-6f);
#pragma unroll
            for (int nt = 0; nt < 4; nt++) {
                c[mt][nt][0] *= i0; c[mt][nt][1] *= i0;
                c[mt][nt][2] *= i1; c[mt][nt][3] *= i1;
            }
        }
    }

#pragma unroll
    for (int mt = 0; mt < 2; mt++)
#pragma unroll
        for (int nt = 0; nt < 4; nt++) {
            int col = n0 + nbase + nt*8 + t4*2;
            size_t r0 = (size_t)(m0 + mbase + mt*16 + g);
            size_t r1 = r0 + 8;
            float v0 = c[mt][nt][0], v1 = c[mt][nt][1];
            float v2 = c[mt][nt][2], v3 = c[mt][nt][3];
            if (mode == 1) {
                v0 = 0.5f*v0*(1.f + erff(v0*0.70710678118654752f));
                v1 = 0.5f*v1*(1.f + erff(v1*0.70710678118654752f));
                v2 = 0.5f*v2*(1.f + erff(v2*0.70710678118654752f));
                v3 = 0.5f*v3*(1.f + erff(v3*0.70710678118654752f));
            }
            if (res) {
                v0 += res[r0*N + col]; v1 += res[r0*N + col + 1];
                v2 += res[r1*N + col]; v3 += res[r1*N + col + 1];
            }
            *(float2*)&C[r0*N + col] = make_float2(v0, v1);
            *(float2*)&C[r1*N + col] = make_float2(v2, v3);
        }
}

// ---------------- launch ----------------
extern "C" void kernel_launch(void* const* d_in, const int* in_sizes, int n_in,
                              void* d_out, int out_size) {
    const float* vis   = (const float*)d_in[0];
    const float* text  = (const float*)d_in[1];
    const float* Wq    = (const float*)d_in[2];
    const float* bq    = (const float*)d_in[3];
    const float* Wk    = (const float*)d_in[4];
    const float* bk    = (const float*)d_in[5];
    const float* Wv    = (const float*)d_in[6];
    const float* bv    = (const float*)d_in[7];
    const float* Wo    = (const float*)d_in[8];
    const float* bo    = (const float*)d_in[9];
    const float* g1    = (const float*)d_in[10];
    const float* b1    = (const float*)d_in[11];
    const float* g2    = (const float*)d_in[12];
    const float* b2    = (const float*)d_in[13];
    const float* Wf1   = (const float*)d_in[14];
    const float* bf1   = (const float*)d_in[15];
    const float* Wf2   = (const float*)d_in[16];
    const float* bf2   = (const float*)d_in[17];
    const float* ls    = (const float*)d_in[18];
    const float* alpha = (const float*)d_in[19];
    float* out = (float*)d_out;

    float *px, *pq, *paligned, *pproj, *py2, *phdn;
    cudaGetSymbolAddress((void**)&px,       g_x);
    cudaGetSymbolAddress((void**)&pq,       g_q);
    cudaGetSymbolAddress((void**)&paligned, g_aligned);
    cudaGetSymbolAddress((void**)&pproj,    g_proj);
    cudaGetSymbolAddress((void**)&py2,      g_y2);
    cudaGetSymbolAddress((void**)&phdn,     g_hdn);

    ln1_kernel<<<ROWS/8, 256>>>(vis, g1, b1);
    kv_kernel<<<NB*NT/TB, 256>>>(text, Wk, bk, Wv, bv);
    gemm_bf16s_kernel<<<dim3(CVD/64, ROWS/128), 256>>>(px, Wq, bq, nullptr, pq, ROWS, CVD, CVD, 2);
    attn_kernel<<<ROWS/2, 256>>>(ls);
    gemm_bf16s_kernel<<<dim3(CVD/64, ROWS/128), 256>>>(paligned, Wo, bo, nullptr, pproj, ROWS, CVD, CVD, 0);
    ln2res_kernel<<<ROWS/8, 256>>>(g2, b2, alpha);
    gemm_bf16s_kernel<<<dim3(4*CVD/64, ROWS/128), 256>>>(py2, Wf1, bf1, nullptr, phdn, ROWS, 4*CVD, CVD, 1);
    gemm_bf16s_kernel<<<dim3(CVD/64, ROWS/128), 256>>>(phdn, Wf2, bf2, py2, out, ROWS, CVD, 4*CVD, 0);
}

// round 13
// speedup vs baseline: 1.0371x; 1.0371x over previous
#include <cuda_runtime.h>
#include <cuda_bf16.h>
#include <math.h>
#include <stdint.h>

// ---------------- problem constants ----------------
#define NB   8
#define NN   4096          // H*W
#define CVD  256
#define CTD  512
#define NT   77
#define TPAD 96
#define NHH  8
#define DH   32
#define TOPM 5
#define ROWS (NB*NN)       // 32768
#define TB   2             // tokens per kv block

// ---------------- scratch (device globals; no allocs allowed) ----------------
__device__ float g_x[ROWS*CVD];          // LN1 output
__device__ float g_q[ROWS*CVD];          // q projection (l2-normed in epilogue)
__device__ float g_kT[NB*NHH*DH*TPAD];   // k transposed [b][h][d][t]
__device__ float g_v[NB*NT*CVD];         // v
__device__ int   g_pad[NB*NT];           // pad flags
__device__ float g_aligned[ROWS*CVD];    // attention output
__device__ float g_proj[ROWS*CVD];       // aligned @ Wo + bo
__device__ float g_y2[ROWS*CVD];         // LN2 output
__device__ float g_hdn[ROWS*4*CVD];      // FFN hidden (gelu)

// ---------------- LN1 ----------------
__global__ __launch_bounds__(256) void ln1_kernel(const float* __restrict__ in,
                                                  const float* __restrict__ g,
                                                  const float* __restrict__ b) {
    int warp = (blockIdx.x * blockDim.x + threadIdx.x) >> 5;
    int lane = threadIdx.x & 31;
    const float* row = in + (size_t)warp * CVD;
    float v[8]; float s = 0.f, ss = 0.f;
#pragma unroll
    for (int i = 0; i < 8; i++) { v[i] = row[lane*8 + i]; s += v[i]; ss += v[i]*v[i]; }
#pragma unroll
    for (int o = 16; o; o >>= 1) { s += __shfl_xor_sync(~0u, s, o); ss += __shfl_xor_sync(~0u, ss, o); }
    float mu  = s * (1.f/CVD);
    float var = ss * (1.f/CVD) - mu*mu;
    float inv = rsqrtf(var + 1e-5f);
    float* orow = g_x + (size_t)warp * CVD;
#pragma unroll
    for (int i = 0; i < 8; i++) { int c = lane*8 + i; orow[c] = (v[i]-mu)*inv*g[c] + b[c]; }
}

// ---------------- LN2 + residual ----------------
__global__ __launch_bounds__(256) void ln2res_kernel(const float* __restrict__ g,
                                                     const float* __restrict__ b,
                                                     const float* __restrict__ alpha_p) {
    int warp = (blockIdx.x * blockDim.x + threadIdx.x) >> 5;
    int lane = threadIdx.x & 31;
    float alpha = alpha_p[0];
    const float* xr = g_x    + (size_t)warp * CVD;
    const float* pr = g_proj + (size_t)warp * CVD;
    float v[8]; float s = 0.f, ss = 0.f;
#pragma unroll
    for (int i = 0; i < 8; i++) {
        int c = lane*8 + i;
        v[i] = xr[c] + alpha * pr[c];
        s += v[i]; ss += v[i]*v[i];
    }
#pragma unroll
    for (int o = 16; o; o >>= 1) { s += __shfl_xor_sync(~0u, s, o); ss += __shfl_xor_sync(~0u, ss, o); }
    float mu  = s * (1.f/CVD);
    float var = ss * (1.f/CVD) - mu*mu;
    float inv = rsqrtf(var + 1e-5f);
    float* orow = g_y2 + (size_t)warp * CVD;
#pragma unroll
    for (int i = 0; i < 8; i++) { int c = lane*8 + i; orow[c] = (v[i]-mu)*inv*g[c] + b[c]; }
}

// ---------------- K/V projection, 2 tokens per block (halved weight traffic, full occupancy) ----------------
__global__ __launch_bounds__(256) void kv_kernel(const float* __restrict__ text,
                                                 const float* __restrict__ Wk, const float* __restrict__ bk,
                                                 const float* __restrict__ Wv, const float* __restrict__ bv) {
    int bt0 = blockIdx.x * TB;
    int c   = threadIdx.x;
    int wid = c >> 5, lane = c & 31;
    __shared__ float txt[TB][CTD];

    for (int i = c; i < TB*CTD; i += 256) {
        int j = i >> 9, kk = i & 511;
        txt[j][kk] = text[(size_t)(bt0 + j) * CTD + kk];
    }
    __syncthreads();

    // pad flags: warps 0..TB-1 handle one row each (exact for all-zero pad rows)
    if (wid < TB) {
        float sum = 0.f;
        for (int kk = lane; kk < CTD; kk += 32) sum += fabsf(txt[wid][kk]);
#pragma unroll
        for (int o = 16; o; o >>= 1) sum += __shfl_xor_sync(~0u, sum, o);
        if (lane == 0) g_pad[bt0 + wid] = (sum <= 1e-6f);
    }

    float ak[TB], av_[TB];
#pragma unroll
    for (int j = 0; j < TB; j++) { ak[j] = bk[c]; av_[j] = bv[c]; }

#pragma unroll 4
    for (int kk = 0; kk < CTD; kk++) {
        float wk = Wk[kk*CVD + c];
        float wv = Wv[kk*CVD + c];
#pragma unroll
        for (int j = 0; j < TB; j++) {
            float tv = txt[j][kk];
            ak[j]  += tv * wk;
            av_[j] += tv * wv;
        }
    }

    int h = c >> 5, d = c & 31;
#pragma unroll
    for (int j = 0; j < TB; j++) {
        int bt = bt0 + j;
        int b = bt / NT, t = bt - b * NT;
        float kc = ak[j];
        float ss = kc * kc;
#pragma unroll
        for (int o = 16; o; o >>= 1) ss += __shfl_xor_sync(~0u, ss, o);
        kc /= fmaxf(sqrtf(ss), 1e-6f);
        g_kT[((b*NHH + h)*DH + d)*TPAD + t] = kc;
        g_v[(size_t)bt*CVD + c] = av_[j];
    }
}

// ---------------- order-preserving float<->uint ----------------
__device__ __forceinline__ uint32_t ford(float f) {
    uint32_t u = __float_as_uint(f);
    return (u & 0x80000000u) ? ~u : (u | 0x80000000u);
}
__device__ __forceinline__ float finv(uint32_t m) {
    uint32_t u = (m & 0x80000000u) ? (m ^ 0x80000000u) : ~m;
    return __uint_as_float(u);
}

// ---------------- attention: 2 rows per block, warp per head; redux top-5 ----------------
__global__ __launch_bounds__(256) void attn_kernel(const float* __restrict__ logit_scale) {
    int row0 = blockIdx.x * 2;
    int b    = row0 >> 12;
    int tid  = threadIdx.x;
    int h = tid >> 5, lane = tid & 31;
    __shared__ float qs[2][CVD];
    __shared__ int   spad[NT];
    qs[0][tid] = g_q[(size_t)row0 * CVD + tid];
    qs[1][tid] = g_q[(size_t)(row0 + 1) * CVD + tid];
    if (tid < NT) spad[tid] = g_pad[b*NT + tid];
    __syncthreads();

    float ls = logit_scale[0];
    float scale = expf(fminf(fmaxf(ls, -2.f), 2.f)) * 0.17677669529663687f;

    const float* kT = g_kT + ((size_t)(b*NHH + h) * DH) * TPAD;  // [d][t]
    float acc[2][3] = {};
#pragma unroll
    for (int d = 0; d < DH; d++) {
        const float* kr = kT + d*TPAD;
        float k0 = kr[lane], k1 = kr[lane + 32], k2 = kr[lane + 64];
        float q0 = qs[0][h*DH + d];
        float q1 = qs[1][h*DH + d];
        acc[0][0] += q0 * k0; acc[0][1] += q0 * k1; acc[0][2] += q0 * k2;
        acc[1][0] += q1 * k0; acc[1][1] += q1 * k1; acc[1][2] += q1 * k2;
    }

    bool p0 = spad[lane];
    bool p1 = (lane + 32 >= NT) || spad[lane + 32];
    bool p2 = (lane + 64 >= NT) || spad[lane + 64];

#pragma unroll
    for (int rr = 0; rr < 2; rr++) {
        float s0 = !p0 ? acc[rr][0] * scale : -INFINITY;
        float s1 = !p1 ? acc[rr][1] * scale : -INFINITY;
        float s2 = !p2 ? acc[rr][2] * scale : -INFINITY;

        uint32_t o0 = ford(s0), o1 = ford(s1), o2 = ford(s2);

        float topv[TOPM]; int topt[TOPM];
#pragma unroll
        for (int it = 0; it < TOPM; it++) {
            uint32_t loc = o0 > o1 ? o0 : o1;
            if (o2 > loc) loc = o2;
            uint32_t m = __reduce_max_sync(0xffffffffu, loc);
            topv[it] = finv(m);
            int t;
            unsigned b0 = __ballot_sync(0xffffffffu, o0 == m);
            if (b0) t = __ffs(b0) - 1;
            else {
                unsigned b1 = __ballot_sync(0xffffffffu, o1 == m);
                if (b1) t = 32 + __ffs(b1) - 1;
                else {
                    unsigned b2 = __ballot_sync(0xffffffffu, o2 == m);
                    t = 64 + __ffs(b2) - 1;
                }
            }
            topt[it] = t;
            if ((t & 31) == lane) {
                if (t < 32) o0 = 0u; else if (t < 64) o1 = 0u; else o2 = 0u;
            }
        }

        float outv = 0.f;
        float mx = topv[0];
        if (!(mx == -INFINITY)) {
            float e[TOPM]; float ws = 0.f;
#pragma unroll
            for (int i = 0; i < TOPM; i++) { e[i] = expf(topv[i] - mx); ws += e[i]; }
            float inv = 1.f / ws;
            const float* vb = g_v + (size_t)b * NT * CVD + h * DH + lane;
#pragma unroll
            for (int i = 0; i < TOPM; i++) outv += (e[i] * inv) * vb[(size_t)topt[i] * CVD];
        }
        g_aligned[(size_t)(row0 + rr) * CVD + h*DH + lane] = outv;
    }
}

// ---------------- bf16 split helpers ----------------
__device__ __forceinline__ void bf16_split_pack(float x0, float x1, uint32_t& hi, uint32_t& lo) {
    __nv_bfloat16 h0 = __float2bfloat16_rn(x0);
    __nv_bfloat16 h1 = __float2bfloat16_rn(x1);
    __nv_bfloat16 l0 = __float2bfloat16_rn(x0 - __bfloat162float(h0));
    __nv_bfloat16 l1 = __float2bfloat16_rn(x1 - __bfloat162float(h1));
    hi = (uint32_t)__bfloat16_as_ushort(h0) | ((uint32_t)__bfloat16_as_ushort(h1) << 16);
    lo = (uint32_t)__bfloat16_as_ushort(l0) | ((uint32_t)__bfloat16_as_ushort(l1) << 16);
}
__device__ __forceinline__ void mma16(float* c, const uint32_t* a, const uint32_t* b) {
    asm volatile("mma.sync.aligned.m16n8k16.row.col.f32.bf16.bf16.f32 "
        "{%0,%1,%2,%3}, {%4,%5,%6,%7}, {%8,%9}, {%0,%1,%2,%3};"
        : "+f"(c[0]), "+f"(c[1]), "+f"(c[2]), "+f"(c[3])
        : "r"(a[0]), "r"(a[1]), "r"(a[2]), "r"(a[3]), "r"(b[0]), "r"(b[1]));
}
__device__ __forceinline__ void ldsm4(uint32_t* r, uint32_t saddr) {
    asm volatile("ldmatrix.sync.aligned.m8n8.x4.shared.b16 {%0,%1,%2,%3}, [%4];"
        : "=r"(r[0]), "=r"(r[1]), "=r"(r[2]), "=r"(r[3]) : "r"(saddr));
}

// ---------------- split-bf16 GEMM, A fragments via ldmatrix (unchanged from R10) ----------------
#define ASTRIDE 12
__global__ __launch_bounds__(256) void gemm_bf16s_kernel(const float* __restrict__ A,
                                                         const float* __restrict__ B,
                                                         const float* __restrict__ bias,
                                                         const float* __restrict__ res,
                                                         float* __restrict__ C,
                                                         int M, int N, int K, int mode) {
    __shared__ uint32_t AhS[2][128*ASTRIDE], AlS[2][128*ASTRIDE];
    __shared__ uint32_t Bh[2][8][72],  Bl[2][8][72];

    int tid  = threadIdx.x;
    int lane = tid & 31, wid = tid >> 5;
    int warpM = wid & 3, warpN = wid >> 2;
    int g = lane >> 2, t4 = lane & 3;
    int m0 = blockIdx.y * 128, n0 = blockIdx.x * 64;
    int mbase = warpM * 32, nbase = warpN * 32;

    float c[2][4][4];
#pragma unroll
    for (int i = 0; i < 2; i++)
#pragma unroll
        for (int j = 0; j < 4; j++)
#pragma unroll
            for (int l = 0; l < 4; l++) c[i][j][l] = 0.f;

    int ar   = tid >> 1;
    int ha   = tid & 1;
    int aoff = ar * ASTRIDE + ha * 4;
    int bn   = tid & 63;
    int k2b  = (tid >> 6) * 2;
    const float* Aptr = A + (size_t)(m0 + ar) * K + 8*ha;
    const float* Bptr = B + (size_t)(2*k2b) * N + n0 + bn;

    int lrow = lane & 15;
    int lkof = (lane >> 4) * 4;

    float4 av0, av1;
    float  b00, b01, b10, b11;
    av0 = *(const float4*)(Aptr);
    av1 = *(const float4*)(Aptr + 4);
    b00 = Bptr[0]; b01 = Bptr[N]; b10 = Bptr[2*N]; b11 = Bptr[3*N];

    {
        uint32_t h0,l0,h1,l1,h2,l2,h3,l3;
        bf16_split_pack(av0.x, av0.y, h0, l0);
        bf16_split_pack(av0.z, av0.w, h1, l1);
        bf16_split_pack(av1.x, av1.y, h2, l2);
        bf16_split_pack(av1.z, av1.w, h3, l3);
        *(uint4*)&AhS[0][aoff] = make_uint4(h0, h1, h2, h3);
        *(uint4*)&AlS[0][aoff] = make_uint4(l0, l1, l2, l3);
        uint32_t h, l;
        bf16_split_pack(b00, b01, h, l); Bh[0][k2b  ][bn] = h; Bl[0][k2b  ][bn] = l;
        bf16_split_pack(b10, b11, h, l); Bh[0][k2b+1][bn] = h; Bl[0][k2b+1][bn] = l;
    }

    int stage = 0;
    for (int k0 = 0; k0 < K; k0 += 16) {
        __syncthreads();
        bool more = (k0 + 16) < K;
        if (more) {
            av0 = *(const float4*)(Aptr + k0 + 16);
            av1 = *(const float4*)(Aptr + k0 + 20);
            const float* bp = Bptr + (size_t)(k0 + 16) * N;
            b00 = bp[0]; b01 = bp[N]; b10 = bp[2*N]; b11 = bp[3*N];
        }

        uint32_t ah[2][4], al[2][4], bh[4][2], blo[4][2];
#pragma unroll
        for (int mt = 0; mt < 2; mt++) {
            int r = mbase + mt*16 + lrow;
            uint32_t addrH = (uint32_t)__cvta_generic_to_shared(&AhS[stage][r*ASTRIDE + lkof]);
            uint32_t addrL = (uint32_t)__cvta_generic_to_shared(&AlS[stage][r*ASTRIDE + lkof]);
            ldsm4(ah[mt], addrH);
            ldsm4(al[mt], addrL);
        }
#pragma unroll
        for (int nt = 0; nt < 4; nt++) {
            int cn = nbase + nt*8 + g;
            bh[nt][0]  = Bh[stage][t4][cn];    bh[nt][1]  = Bh[stage][t4+4][cn];
            blo[nt][0] = Bl[stage][t4][cn];    blo[nt][1] = Bl[stage][t4+4][cn];
        }
#pragma unroll
        for (int mt = 0; mt < 2; mt++)
#pragma unroll
            for (int nt = 0; nt < 4; nt++) {
                mma16(c[mt][nt], al[mt], bh[nt]);
                mma16(c[mt][nt], ah[mt], blo[nt]);
                mma16(c[mt][nt], ah[mt], bh[nt]);
            }

        if (more) {
            int ns = stage ^ 1;
            uint32_t h0,l0,h1,l1,h2,l2,h3,l3;
            bf16_split_pack(av0.x, av0.y, h0, l0);
            bf16_split_pack(av0.z, av0.w, h1, l1);
            bf16_split_pack(av1.x, av1.y, h2, l2);
            bf16_split_pack(av1.z, av1.w, h3, l3);
            *(uint4*)&AhS[ns][aoff] = make_uint4(h0, h1, h2, h3);
            *(uint4*)&AlS[ns][aoff] = make_uint4(l0, l1, l2, l3);
            uint32_t h, l;
            bf16_split_pack(b00, b01, h, l); Bh[ns][k2b  ][bn] = h; Bl[ns][k2b  ][bn] = l;
            bf16_split_pack(b10, b11, h, l); Bh[ns][k2b+1][bn] = h; Bl[ns][k2b+1][bn] = l;
        }
        stage ^= 1;
    }

#pragma unroll
    for (int mt = 0; mt < 2; mt++)
#pragma unroll
        for (int nt = 0; nt < 4; nt++) {
            int col = n0 + nbase + nt*8 + t4*2;
            float b0v = bias[col], b1v = bias[col + 1];
            c[mt][nt][0] += b0v; c[mt][nt][1] += b1v;
            c[mt][nt][2] += b0v; c[mt][nt][3] += b1v;
        }

    if (mode == 2) {
#pragma unroll
        for (int mt = 0; mt < 2; mt++) {
            float ss0 = 0.f, ss1 = 0.f;
#pragma unroll
            for (int nt = 0; nt < 4; nt++) {
                ss0 += c[mt][nt][0]*c[mt][nt][0] + c[mt][nt][1]*c[mt][nt][1];
                ss1 += c[mt][nt][2]*c[mt][nt][2] + c[mt][nt][3]*c[mt][nt][3];
            }
            ss0 += __shfl_xor_sync(~0u, ss0, 1); ss0 += __shfl_xor_sync(~0u, ss0, 2);
            ss1 += __shfl_xor_sync(~0u, ss1, 1); ss1 += __shfl_xor_sync(~0u, ss1, 2);
            float i0 = 1.f / fmaxf(sqrtf(ss0), 1e-6f);
            float i1 = 1.f / fmaxf(sqrtf(ss1), 1e-6f);
#pragma unroll
            for (int nt = 0; nt < 4; nt++) {
                c[mt][nt][0] *= i0; c[mt][nt][1] *= i0;
                c[mt][nt][2] *= i1; c[mt][nt][3] *= i1;
            }
        }
    }

#pragma unroll
    for (int mt = 0; mt < 2; mt++)
#pragma unroll
        for (int nt = 0; nt < 4; nt++) {
            int col = n0 + nbase + nt*8 + t4*2;
            size_t r0 = (size_t)(m0 + mbase + mt*16 + g);
            size_t r1 = r0 + 8;
            float v0 = c[mt][nt][0], v1 = c[mt][nt][1];
            float v2 = c[mt][nt][2], v3 = c[mt][nt][3];
            if (mode == 1) {
                v0 = 0.5f*v0*(1.f + erff(v0*0.70710678118654752f));
                v1 = 0.5f*v1*(1.f + erff(v1*0.70710678118654752f));
                v2 = 0.5f*v2*(1.f + erff(v2*0.70710678118654752f));
                v3 = 0.5f*v3*(1.f + erff(v3*0.70710678118654752f));
            }
            if (res) {
                v0 += res[r0*N + col]; v1 += res[r0*N + col + 1];
                v2 += res[r1*N + col]; v3 += res[r1*N + col + 1];
            }
            *(float2*)&C[r0*N + col] = make_float2(v0, v1);
            *(float2*)&C[r1*N + col] = make_float2(v2, v3);
        }
}

// ---------------- launch ----------------
extern "C" void kernel_launch(void* const* d_in, const int* in_sizes, int n_in,
                              void* d_out, int out_size) {
    const float* vis   = (const float*)d_in[0];
    const float* text  = (const float*)d_in[1];
    const float* Wq    = (const float*)d_in[2];
    const float* bq    = (const float*)d_in[3];
    const float* Wk    = (const float*)d_in[4];
    const float* bk    = (const float*)d_in[5];
    const float* Wv    = (const float*)d_in[6];
    const float* bv    = (const float*)d_in[7];
    const float* Wo    = (const float*)d_in[8];
    const float* bo    = (const float*)d_in[9];
    const float* g1    = (const float*)d_in[10];
    const float* b1    = (const float*)d_in[11];
    const float* g2    = (const float*)d_in[12];
    const float* b2    = (const float*)d_in[13];
    const float* Wf1   = (const float*)d_in[14];
    const float* bf1   = (const float*)d_in[15];
    const float* Wf2   = (const float*)d_in[16];
    const float* bf2   = (const float*)d_in[17];
    const float* ls    = (const float*)d_in[18];
    const float* alpha = (const float*)d_in[19];
    float* out = (float*)d_out;

    float *px, *pq, *paligned, *pproj, *py2, *phdn;
    cudaGetSymbolAddress((void**)&px,       g_x);
    cudaGetSymbolAddress((void**)&pq,       g_q);
    cudaGetSymbolAddress((void**)&paligned, g_aligned);
    cudaGetSymbolAddress((void**)&pproj,    g_proj);
    cudaGetSymbolAddress((void**)&py2,      g_y2);
    cudaGetSymbolAddress((void**)&phdn,     g_hdn);

    ln1_kernel<<<ROWS/8, 256>>>(vis, g1, b1);
    kv_kernel<<<NB*NT/TB, 256>>>(text, Wk, bk, Wv, bv);
    gemm_bf16s_kernel<<<dim3(CVD/64, ROWS/128), 256>>>(px, Wq, bq, nullptr, pq, ROWS, CVD, CVD, 2);
    attn_kernel<<<ROWS/2, 256>>>(ls);
    gemm_bf16s_kernel<<<dim3(CVD/64, ROWS/128), 256>>>(paligned, Wo, bo, nullptr, pproj, ROWS, CVD, CVD, 0);
    ln2res_kernel<<<ROWS/8, 256>>>(g2, b2, alpha);
    gemm_bf16s_kernel<<<dim3(4*CVD/64, ROWS/128), 256>>>(py2, Wf1, bf1, nullptr, phdn, ROWS, 4*CVD, CVD, 1);
    gemm_bf16s_kernel<<<dim3(CVD/64, ROWS/128), 256>>>(phdn, Wf2, bf2, py2, out, ROWS, CVD, 4*CVD, 0);
}

// round 14
// speedup vs baseline: 1.0819x; 1.0432x over previous
#include <cuda_runtime.h>
#include <cuda_bf16.h>
#include <math.h>
#include <stdint.h>

// ---------------- problem constants ----------------
#define NB   8
#define NN   4096          // H*W
#define CVD  256
#define CTD  512
#define NT   77
#define TPAD 96
#define NHH  8
#define DH   32
#define TOPM 5
#define ROWS (NB*NN)       // 32768

// ---------------- scratch (device globals; no allocs allowed) ----------------
__device__ float g_x[ROWS*CVD];          // LN1 output
__device__ float g_q[ROWS*CVD];          // q projection (l2-normed in epilogue)
__device__ float g_kT[NB*NHH*DH*TPAD];   // k transposed [b][h][d][t]
__device__ float g_v[NB*NT*CVD];         // v
__device__ int   g_pad[NB*NT];           // pad flags
__device__ float g_aligned[ROWS*CVD];    // attention output
__device__ float g_proj[ROWS*CVD];       // aligned @ Wo + bo
__device__ float g_y2[ROWS*CVD];         // LN2 output
__device__ float g_hdn[ROWS*4*CVD];      // FFN hidden (gelu)

// ---------------- LN1 ----------------
__global__ __launch_bounds__(256) void ln1_kernel(const float* __restrict__ in,
                                                  const float* __restrict__ g,
                                                  const float* __restrict__ b) {
    int warp = (blockIdx.x * blockDim.x + threadIdx.x) >> 5;
    int lane = threadIdx.x & 31;
    const float* row = in + (size_t)warp * CVD;
    float v[8]; float s = 0.f, ss = 0.f;
#pragma unroll
    for (int i = 0; i < 8; i++) { v[i] = row[lane*8 + i]; s += v[i]; ss += v[i]*v[i]; }
#pragma unroll
    for (int o = 16; o; o >>= 1) { s += __shfl_xor_sync(~0u, s, o); ss += __shfl_xor_sync(~0u, ss, o); }
    float mu  = s * (1.f/CVD);
    float var = ss * (1.f/CVD) - mu*mu;
    float inv = rsqrtf(var + 1e-5f);
    float* orow = g_x + (size_t)warp * CVD;
#pragma unroll
    for (int i = 0; i < 8; i++) { int c = lane*8 + i; orow[c] = (v[i]-mu)*inv*g[c] + b[c]; }
}

// ---------------- LN2 + residual ----------------
__global__ __launch_bounds__(256) void ln2res_kernel(const float* __restrict__ g,
                                                     const float* __restrict__ b,
                                                     const float* __restrict__ alpha_p) {
    int warp = (blockIdx.x * blockDim.x + threadIdx.x) >> 5;
    int lane = threadIdx.x & 31;
    float alpha = alpha_p[0];
    const float* xr = g_x    + (size_t)warp * CVD;
    const float* pr = g_proj + (size_t)warp * CVD;
    float v[8]; float s = 0.f, ss = 0.f;
#pragma unroll
    for (int i = 0; i < 8; i++) {
        int c = lane*8 + i;
        v[i] = xr[c] + alpha * pr[c];
        s += v[i]; ss += v[i]*v[i];
    }
#pragma unroll
    for (int o = 16; o; o >>= 1) { s += __shfl_xor_sync(~0u, s, o); ss += __shfl_xor_sync(~0u, ss, o); }
    float mu  = s * (1.f/CVD);
    float var = ss * (1.f/CVD) - mu*mu;
    float inv = rsqrtf(var + 1e-5f);
    float* orow = g_y2 + (size_t)warp * CVD;
#pragma unroll
    for (int i = 0; i < 8; i++) { int c = lane*8 + i; orow[c] = (v[i]-mu)*inv*g[c] + b[c]; }
}

// ---------------- K/V projection + pad flags + k l2norm + K transpose (per-token, R10) ----------------
__global__ __launch_bounds__(256) void kv_kernel(const float* __restrict__ text,
                                                 const float* __restrict__ Wk, const float* __restrict__ bk,
                                                 const float* __restrict__ Wv, const float* __restrict__ bv) {
    int bt = blockIdx.x;          // b*NT + t
    int b  = bt / NT, t = bt - b * NT;
    int c  = threadIdx.x;
    __shared__ float txt[CTD];
    __shared__ float red[256];
    const float* trow = text + (size_t)bt * CTD;
    txt[c] = trow[c]; txt[c+256] = trow[c+256];
    __syncthreads();
    red[c] = fabsf(txt[c]) + fabsf(txt[c+256]);
    __syncthreads();
    for (int s = 128; s; s >>= 1) { if (c < s) red[c] += red[c+s]; __syncthreads(); }
    if (c == 0) g_pad[bt] = (red[0] <= 1e-6f);
    float kc = bk[c], vc = bv[c];
#pragma unroll 4
    for (int kk = 0; kk < CTD; kk++) {
        float tv = txt[kk];
        kc += tv * Wk[kk*CVD + c];
        vc += tv * Wv[kk*CVD + c];
    }
    float ss = kc * kc;
#pragma unroll
    for (int o = 16; o; o >>= 1) ss += __shfl_xor_sync(~0u, ss, o);
    kc /= fmaxf(sqrtf(ss), 1e-6f);
    int h = c >> 5, d = c & 31;
    g_kT[((b*NHH + h)*DH + d)*TPAD + t] = kc;
    g_v[(size_t)bt*CVD + c] = vc;
}

// ---------------- order-preserving float<->uint ----------------
__device__ __forceinline__ uint32_t ford(float f) {
    uint32_t u = __float_as_uint(f);
    return (u & 0x80000000u) ? ~u : (u | 0x80000000u);
}
__device__ __forceinline__ float finv(uint32_t m) {
    uint32_t u = (m & 0x80000000u) ? (m ^ 0x80000000u) : ~m;
    return __uint_as_float(u);
}

// ---------------- attention: 2 rows per block, warp per head; redux top-5 ----------------
__global__ __launch_bounds__(256) void attn_kernel(const float* __restrict__ logit_scale) {
    int row0 = blockIdx.x * 2;
    int b    = row0 >> 12;
    int tid  = threadIdx.x;
    int h = tid >> 5, lane = tid & 31;
    __shared__ float qs[2][CVD];
    __shared__ int   spad[NT];
    qs[0][tid] = g_q[(size_t)row0 * CVD + tid];
    qs[1][tid] = g_q[(size_t)(row0 + 1) * CVD + tid];
    if (tid < NT) spad[tid] = g_pad[b*NT + tid];
    __syncthreads();

    float ls = logit_scale[0];
    float scale = expf(fminf(fmaxf(ls, -2.f), 2.f)) * 0.17677669529663687f;

    const float* kT = g_kT + ((size_t)(b*NHH + h) * DH) * TPAD;  // [d][t]
    float acc[2][3] = {};
#pragma unroll
    for (int d = 0; d < DH; d++) {
        const float* kr = kT + d*TPAD;
        float k0 = kr[lane], k1 = kr[lane + 32], k2 = kr[lane + 64];
        float q0 = qs[0][h*DH + d];
        float q1 = qs[1][h*DH + d];
        acc[0][0] += q0 * k0; acc[0][1] += q0 * k1; acc[0][2] += q0 * k2;
        acc[1][0] += q1 * k0; acc[1][1] += q1 * k1; acc[1][2] += q1 * k2;
    }

    bool p0 = spad[lane];
    bool p1 = (lane + 32 >= NT) || spad[lane + 32];
    bool p2 = (lane + 64 >= NT) || spad[lane + 64];

#pragma unroll
    for (int rr = 0; rr < 2; rr++) {
        float s0 = !p0 ? acc[rr][0] * scale : -INFINITY;
        float s1 = !p1 ? acc[rr][1] * scale : -INFINITY;
        float s2 = !p2 ? acc[rr][2] * scale : -INFINITY;

        uint32_t o0 = ford(s0), o1 = ford(s1), o2 = ford(s2);

        float topv[TOPM]; int topt[TOPM];
#pragma unroll
        for (int it = 0; it < TOPM; it++) {
            uint32_t loc = o0 > o1 ? o0 : o1;
            if (o2 > loc) loc = o2;
            uint32_t m = __reduce_max_sync(0xffffffffu, loc);
            topv[it] = finv(m);
            int t;
            unsigned b0 = __ballot_sync(0xffffffffu, o0 == m);
            if (b0) t = __ffs(b0) - 1;
            else {
                unsigned b1 = __ballot_sync(0xffffffffu, o1 == m);
                if (b1) t = 32 + __ffs(b1) - 1;
                else {
                    unsigned b2 = __ballot_sync(0xffffffffu, o2 == m);
                    t = 64 + __ffs(b2) - 1;
                }
            }
            topt[it] = t;
            if ((t & 31) == lane) {
                if (t < 32) o0 = 0u; else if (t < 64) o1 = 0u; else o2 = 0u;
            }
        }

        float outv = 0.f;
        float mx = topv[0];
        if (!(mx == -INFINITY)) {
            float e[TOPM]; float ws = 0.f;
#pragma unroll
            for (int i = 0; i < TOPM; i++) { e[i] = expf(topv[i] - mx); ws += e[i]; }
            float inv = 1.f / ws;
            const float* vb = g_v + (size_t)b * NT * CVD + h * DH + lane;
#pragma unroll
            for (int i = 0; i < TOPM; i++) outv += (e[i] * inv) * vb[(size_t)topt[i] * CVD];
        }
        g_aligned[(size_t)(row0 + rr) * CVD + h*DH + lane] = outv;
    }
}

// ---------------- bf16 split helpers ----------------
__device__ __forceinline__ void bf16_split_pack(float x0, float x1, uint32_t& hi, uint32_t& lo) {
    __nv_bfloat16 h0 = __float2bfloat16_rn(x0);
    __nv_bfloat16 h1 = __float2bfloat16_rn(x1);
    __nv_bfloat16 l0 = __float2bfloat16_rn(x0 - __bfloat162float(h0));
    __nv_bfloat16 l1 = __float2bfloat16_rn(x1 - __bfloat162float(h1));
    hi = (uint32_t)__bfloat16_as_ushort(h0) | ((uint32_t)__bfloat16_as_ushort(h1) << 16);
    lo = (uint32_t)__bfloat16_as_ushort(l0) | ((uint32_t)__bfloat16_as_ushort(l1) << 16);
}
__device__ __forceinline__ void mma16(float* c, const uint32_t* a, const uint32_t* b) {
    asm volatile("mma.sync.aligned.m16n8k16.row.col.f32.bf16.bf16.f32 "
        "{%0,%1,%2,%3}, {%4,%5,%6,%7}, {%8,%9}, {%0,%1,%2,%3};"
        : "+f"(c[0]), "+f"(c[1]), "+f"(c[2]), "+f"(c[3])
        : "r"(a[0]), "r"(a[1]), "r"(a[2]), "r"(a[3]), "r"(b[0]), "r"(b[1]));
}
__device__ __forceinline__ void ldsm4(uint32_t* r, uint32_t saddr) {
    asm volatile("ldmatrix.sync.aligned.m8n8.x4.shared.b16 {%0,%1,%2,%3}, [%4];"
        : "=r"(r[0]), "=r"(r[1]), "=r"(r[2]), "=r"(r[3]) : "r"(saddr));
}

// ---------------- split-bf16 GEMM, A fragments via ldmatrix (unchanged from R10) ----------------
#define ASTRIDE 12
__global__ __launch_bounds__(256) void gemm_bf16s_kernel(const float* __restrict__ A,
                                                         const float* __restrict__ B,
                                                         const float* __restrict__ bias,
                                                         const float* __restrict__ res,
                                                         float* __restrict__ C,
                                                         int M, int N, int K, int mode) {
    __shared__ uint32_t AhS[2][128*ASTRIDE], AlS[2][128*ASTRIDE];
    __shared__ uint32_t Bh[2][8][72],  Bl[2][8][72];

    int tid  = threadIdx.x;
    int lane = tid & 31, wid = tid >> 5;
    int warpM = wid & 3, warpN = wid >> 2;
    int g = lane >> 2, t4 = lane & 3;
    int m0 = blockIdx.y * 128, n0 = blockIdx.x * 64;
    int mbase = warpM * 32, nbase = warpN * 32;

    float c[2][4][4];
#pragma unroll
    for (int i = 0; i < 2; i++)
#pragma unroll
        for (int j = 0; j < 4; j++)
#pragma unroll
            for (int l = 0; l < 4; l++) c[i][j][l] = 0.f;

    int ar   = tid >> 1;
    int ha   = tid & 1;
    int aoff = ar * ASTRIDE + ha * 4;
    int bn   = tid & 63;
    int k2b  = (tid >> 6) * 2;
    const float* Aptr = A + (size_t)(m0 + ar) * K + 8*ha;
    const float* Bptr = B + (size_t)(2*k2b) * N + n0 + bn;

    int lrow = lane & 15;
    int lkof = (lane >> 4) * 4;

    float4 av0, av1;
    float  b00, b01, b10, b11;
    av0 = *(const float4*)(Aptr);
    av1 = *(const float4*)(Aptr + 4);
    b00 = Bptr[0]; b01 = Bptr[N]; b10 = Bptr[2*N]; b11 = Bptr[3*N];

    {
        uint32_t h0,l0,h1,l1,h2,l2,h3,l3;
        bf16_split_pack(av0.x, av0.y, h0, l0);
        bf16_split_pack(av0.z, av0.w, h1, l1);
        bf16_split_pack(av1.x, av1.y, h2, l2);
        bf16_split_pack(av1.z, av1.w, h3, l3);
        *(uint4*)&AhS[0][aoff] = make_uint4(h0, h1, h2, h3);
        *(uint4*)&AlS[0][aoff] = make_uint4(l0, l1, l2, l3);
        uint32_t h, l;
        bf16_split_pack(b00, b01, h, l); Bh[0][k2b  ][bn] = h; Bl[0][k2b  ][bn] = l;
        bf16_split_pack(b10, b11, h, l); Bh[0][k2b+1][bn] = h; Bl[0][k2b+1][bn] = l;
    }

    int stage = 0;
    for (int k0 = 0; k0 < K; k0 += 16) {
        __syncthreads();
        bool more = (k0 + 16) < K;
        if (more) {
            av0 = *(const float4*)(Aptr + k0 + 16);
            av1 = *(const float4*)(Aptr + k0 + 20);
            const float* bp = Bptr + (size_t)(k0 + 16) * N;
            b00 = bp[0]; b01 = bp[N]; b10 = bp[2*N]; b11 = bp[3*N];
        }

        uint32_t ah[2][4], al[2][4], bh[4][2], blo[4][2];
#pragma unroll
        for (int mt = 0; mt < 2; mt++) {
            int r = mbase + mt*16 + lrow;
            uint32_t addrH = (uint32_t)__cvta_generic_to_shared(&AhS[stage][r*ASTRIDE + lkof]);
            uint32_t addrL = (uint32_t)__cvta_generic_to_shared(&AlS[stage][r*ASTRIDE + lkof]);
            ldsm4(ah[mt], addrH);
            ldsm4(al[mt], addrL);
        }
#pragma unroll
        for (int nt = 0; nt < 4; nt++) {
            int cn = nbase + nt*8 + g;
            bh[nt][0]  = Bh[stage][t4][cn];    bh[nt][1]  = Bh[stage][t4+4][cn];
            blo[nt][0] = Bl[stage][t4][cn];    blo[nt][1] = Bl[stage][t4+4][cn];
        }
#pragma unroll
        for (int mt = 0; mt < 2; mt++)
#pragma unroll
            for (int nt = 0; nt < 4; nt++) {
                mma16(c[mt][nt], al[mt], bh[nt]);
                mma16(c[mt][nt], ah[mt], blo[nt]);
                mma16(c[mt][nt], ah[mt], bh[nt]);
            }

        if (more) {
            int ns = stage ^ 1;
            uint32_t h0,l0,h1,l1,h2,l2,h3,l3;
            bf16_split_pack(av0.x, av0.y, h0, l0);
            bf16_split_pack(av0.z, av0.w, h1, l1);
            bf16_split_pack(av1.x, av1.y, h2, l2);
            bf16_split_pack(av1.z, av1.w, h3, l3);
            *(uint4*)&AhS[ns][aoff] = make_uint4(h0, h1, h2, h3);
            *(uint4*)&AlS[ns][aoff] = make_uint4(l0, l1, l2, l3);
            uint32_t h, l;
            bf16_split_pack(b00, b01, h, l); Bh[ns][k2b  ][bn] = h; Bl[ns][k2b  ][bn] = l;
            bf16_split_pack(b10, b11, h, l); Bh[ns][k2b+1][bn] = h; Bl[ns][k2b+1][bn] = l;
        }
        stage ^= 1;
    }

#pragma unroll
    for (int mt = 0; mt < 2; mt++)
#pragma unroll
        for (int nt = 0; nt < 4; nt++) {
            int col = n0 + nbase + nt*8 + t4*2;
            float b0v = bias[col], b1v = bias[col + 1];
            c[mt][nt][0] += b0v; c[mt][nt][1] += b1v;
            c[mt][nt][2] += b0v; c[mt][nt][3] += b1v;
        }

    if (mode == 2) {
#pragma unroll
        for (int mt = 0; mt < 2; mt++) {
            float ss0 = 0.f, ss1 = 0.f;
#pragma unroll
            for (int nt = 0; nt < 4; nt++) {
                ss0 += c[mt][nt][0]*c[mt][nt][0] + c[mt][nt][1]*c[mt][nt][1];
                ss1 += c[mt][nt][2]*c[mt][nt][2] + c[mt][nt][3]*c[mt][nt][3];
            }
            ss0 += __shfl_xor_sync(~0u, ss0, 1); ss0 += __shfl_xor_sync(~0u, ss0, 2);
            ss1 += __shfl_xor_sync(~0u, ss1, 1); ss1 += __shfl_xor_sync(~0u, ss1, 2);
            float i0 = 1.f / fmaxf(sqrtf(ss0), 1e-6f);
            float i1 = 1.f / fmaxf(sqrtf(ss1), 1e-6f);
#pragma unroll
            for (int nt = 0; nt < 4; nt++) {
                c[mt][nt][0] *= i0; c[mt][nt][1] *= i0;
                c[mt][nt][2] *= i1; c[mt][nt][3] *= i1;
            }
        }
    }

#pragma unroll
    for (int mt = 0; mt < 2; mt++)
#pragma unroll
        for (int nt = 0; nt < 4; nt++) {
            int col = n0 + nbase + nt*8 + t4*2;
            size_t r0 = (size_t)(m0 + mbase + mt*16 + g);
            size_t r1 = r0 + 8;
            float v0 = c[mt][nt][0], v1 = c[mt][nt][1];
            float v2 = c[mt][nt][2], v3 = c[mt][nt][3];
            if (mode == 1) {
                v0 = 0.5f*v0*(1.f + erff(v0*0.70710678118654752f));
                v1 = 0.5f*v1*(1.f + erff(v1*0.70710678118654752f));
                v2 = 0.5f*v2*(1.f + erff(v2*0.70710678118654752f));
                v3 = 0.5f*v3*(1.f + erff(v3*0.70710678118654752f));
            }
            if (res) {
                v0 += res[r0*N + col]; v1 += res[r0*N + col + 1];
                v2 += res[r1*N + col]; v3 += res[r1*N + col + 1];
            }
            *(float2*)&C[r0*N + col] = make_float2(v0, v1);
            *(float2*)&C[r1*N + col] = make_float2(v2, v3);
        }
}

// ---------------- launch ----------------
extern "C" void kernel_launch(void* const* d_in, const int* in_sizes, int n_in,
                              void* d_out, int out_size) {
    const float* vis   = (const float*)d_in[0];
    const float* text  = (const float*)d_in[1];
    const float* Wq    = (const float*)d_in[2];
    const float* bq    = (const float*)d_in[3];
    const float* Wk    = (const float*)d_in[4];
    const float* bk    = (const float*)d_in[5];
    const float* Wv    = (const float*)d_in[6];
    const float* bv    = (const float*)d_in[7];
    const float* Wo    = (const float*)d_in[8];
    const float* bo    = (const float*)d_in[9];
    const float* g1    = (const float*)d_in[10];
    const float* b1    = (const float*)d_in[11];
    const float* g2    = (const float*)d_in[12];
    const float* b2    = (const float*)d_in[13];
    const float* Wf1   = (const float*)d_in[14];
    const float* bf1   = (const float*)d_in[15];
    const float* Wf2   = (const float*)d_in[16];
    const float* bf2   = (const float*)d_in[17];
    const float* ls    = (const float*)d_in[18];
    const float* alpha = (const float*)d_in[19];
    float* out = (float*)d_out;

    float *px, *pq, *paligned, *pproj, *py2, *phdn;
    cudaGetSymbolAddress((void**)&px,       g_x);
    cudaGetSymbolAddress((void**)&pq,       g_q);
    cudaGetSymbolAddress((void**)&paligned, g_aligned);
    cudaGetSymbolAddress((void**)&pproj,    g_proj);
    cudaGetSymbolAddress((void**)&py2,      g_y2);
    cudaGetSymbolAddress((void**)&phdn,     g_hdn);

    ln1_kernel<<<ROWS/8, 256>>>(vis, g1, b1);
    kv_kernel<<<NB*NT, 256>>>(text, Wk, bk, Wv, bv);
    gemm_bf16s_kernel<<<dim3(CVD/64, ROWS/128), 256>>>(px, Wq, bq, nullptr, pq, ROWS, CVD, CVD, 2);
    attn_kernel<<<ROWS/2, 256>>>(ls);
    gemm_bf16s_kernel<<<dim3(CVD/64, ROWS/128), 256>>>(paligned, Wo, bo, nullptr, pproj, ROWS, CVD, CVD, 0);
    ln2res_kernel<<<ROWS/8, 256>>>(g2, b2, alpha);
    gemm_bf16s_kernel<<<dim3(4*CVD/64, ROWS/128), 256>>>(py2, Wf1, bf1, nullptr, phdn, ROWS, 4*CVD, CVD, 1);
    gemm_bf16s_kernel<<<dim3(CVD/64, ROWS/128), 256>>>(phdn, Wf2, bf2, py2, out, ROWS, CVD, 4*CVD, 0);
}

// round 15
// speedup vs baseline: 1.1353x; 1.0493x over previous
#include <cuda_runtime.h>
#include <cuda_bf16.h>
#include <math.h>
#include <stdint.h>

// ---------------- problem constants ----------------
#define NB   8
#define NN   4096          // H*W
#define CVD  256
#define CTD  512
#define NT   77
#define TPAD 96
#define NHH  8
#define DH   32
#define TOPM 5
#define ROWS (NB*NN)       // 32768

// ---------------- scratch (device globals; no allocs allowed) ----------------
__device__ float g_x[ROWS*CVD];          // LN1 output
__device__ float g_q[ROWS*CVD];          // q projection (l2-normed in epilogue)
__device__ float g_kT[NB*NHH*DH*TPAD];   // k transposed [b][h][d][t]
__device__ float g_v[NB*NT*CVD];         // v
__device__ int   g_pad[NB*NT];           // pad flags
__device__ float g_aligned[ROWS*CVD];    // attention output
__device__ float g_proj[ROWS*CVD];       // aligned @ Wo + bo
__device__ float g_y2[ROWS*CVD];         // LN2 output
__device__ float g_hdn[ROWS*4*CVD];      // FFN hidden (gelu)

// ---------------- LN1 ----------------
__global__ __launch_bounds__(256) void ln1_kernel(const float* __restrict__ in,
                                                  const float* __restrict__ g,
                                                  const float* __restrict__ b) {
    int warp = (blockIdx.x * blockDim.x + threadIdx.x) >> 5;
    int lane = threadIdx.x & 31;
    const float* row = in + (size_t)warp * CVD;
    float v[8]; float s = 0.f, ss = 0.f;
#pragma unroll
    for (int i = 0; i < 8; i++) { v[i] = row[lane*8 + i]; s += v[i]; ss += v[i]*v[i]; }
#pragma unroll
    for (int o = 16; o; o >>= 1) { s += __shfl_xor_sync(~0u, s, o); ss += __shfl_xor_sync(~0u, ss, o); }
    float mu  = s * (1.f/CVD);
    float var = ss * (1.f/CVD) - mu*mu;
    float inv = rsqrtf(var + 1e-5f);
    float* orow = g_x + (size_t)warp * CVD;
#pragma unroll
    for (int i = 0; i < 8; i++) { int c = lane*8 + i; orow[c] = (v[i]-mu)*inv*g[c] + b[c]; }
}

// ---------------- LN2 + residual ----------------
__global__ __launch_bounds__(256) void ln2res_kernel(const float* __restrict__ g,
                                                     const float* __restrict__ b,
                                                     const float* __restrict__ alpha_p) {
    int warp = (blockIdx.x * blockDim.x + threadIdx.x) >> 5;
    int lane = threadIdx.x & 31;
    float alpha = alpha_p[0];
    const float* xr = g_x    + (size_t)warp * CVD;
    const float* pr = g_proj + (size_t)warp * CVD;
    float v[8]; float s = 0.f, ss = 0.f;
#pragma unroll
    for (int i = 0; i < 8; i++) {
        int c = lane*8 + i;
        v[i] = xr[c] + alpha * pr[c];
        s += v[i]; ss += v[i]*v[i];
    }
#pragma unroll
    for (int o = 16; o; o >>= 1) { s += __shfl_xor_sync(~0u, s, o); ss += __shfl_xor_sync(~0u, ss, o); }
    float mu  = s * (1.f/CVD);
    float var = ss * (1.f/CVD) - mu*mu;
    float inv = rsqrtf(var + 1e-5f);
    float* orow = g_y2 + (size_t)warp * CVD;
#pragma unroll
    for (int i = 0; i < 8; i++) { int c = lane*8 + i; orow[c] = (v[i]-mu)*inv*g[c] + b[c]; }
}

// ---------------- K/V projection + pad flags + k l2norm + K transpose (per-token) ----------------
__global__ __launch_bounds__(256) void kv_kernel(const float* __restrict__ text,
                                                 const float* __restrict__ Wk, const float* __restrict__ bk,
                                                 const float* __restrict__ Wv, const float* __restrict__ bv) {
    int bt = blockIdx.x;          // b*NT + t
    int b  = bt / NT, t = bt - b * NT;
    int c  = threadIdx.x;
    __shared__ float txt[CTD];
    __shared__ float red[256];
    const float* trow = text + (size_t)bt * CTD;
    txt[c] = trow[c]; txt[c+256] = trow[c+256];
    __syncthreads();
    red[c] = fabsf(txt[c]) + fabsf(txt[c+256]);
    __syncthreads();
    for (int s = 128; s; s >>= 1) { if (c < s) red[c] += red[c+s]; __syncthreads(); }
    if (c == 0) g_pad[bt] = (red[0] <= 1e-6f);
    float kc = bk[c], vc = bv[c];
#pragma unroll 4
    for (int kk = 0; kk < CTD; kk++) {
        float tv = txt[kk];
        kc += tv * Wk[kk*CVD + c];
        vc += tv * Wv[kk*CVD + c];
    }
    float ss = kc * kc;
#pragma unroll
    for (int o = 16; o; o >>= 1) ss += __shfl_xor_sync(~0u, ss, o);
    kc /= fmaxf(sqrtf(ss), 1e-6f);
    int h = c >> 5, d = c & 31;
    g_kT[((b*NHH + h)*DH + d)*TPAD + t] = kc;
    g_v[(size_t)bt*CVD + c] = vc;
}

// ---------------- order-preserving float<->uint ----------------
__device__ __forceinline__ uint32_t ford(float f) {
    uint32_t u = __float_as_uint(f);
    return (u & 0x80000000u) ? ~u : (u | 0x80000000u);
}
__device__ __forceinline__ float finv(uint32_t m) {
    uint32_t u = (m & 0x80000000u) ? (m ^ 0x80000000u) : ~m;
    return __uint_as_float(u);
}

// ---------------- attention: 2 rows per block, warp per head; redux top-5 ----------------
__global__ __launch_bounds__(256) void attn_kernel(const float* __restrict__ logit_scale) {
    int row0 = blockIdx.x * 2;
    int b    = row0 >> 12;
    int tid  = threadIdx.x;
    int h = tid >> 5, lane = tid & 31;
    __shared__ float qs[2][CVD];
    __shared__ int   spad[NT];
    qs[0][tid] = g_q[(size_t)row0 * CVD + tid];
    qs[1][tid] = g_q[(size_t)(row0 + 1) * CVD + tid];
    if (tid < NT) spad[tid] = g_pad[b*NT + tid];
    __syncthreads();

    float ls = logit_scale[0];
    float scale = expf(fminf(fmaxf(ls, -2.f), 2.f)) * 0.17677669529663687f;

    const float* kT = g_kT + ((size_t)(b*NHH + h) * DH) * TPAD;  // [d][t]
    float acc[2][3] = {};
#pragma unroll
    for (int d = 0; d < DH; d++) {
        const float* kr = kT + d*TPAD;
        float k0 = kr[lane], k1 = kr[lane + 32], k2 = kr[lane + 64];
        float q0 = qs[0][h*DH + d];
        float q1 = qs[1][h*DH + d];
        acc[0][0] += q0 * k0; acc[0][1] += q0 * k1; acc[0][2] += q0 * k2;
        acc[1][0] += q1 * k0; acc[1][1] += q1 * k1; acc[1][2] += q1 * k2;
    }

    bool p0 = spad[lane];
    bool p1 = (lane + 32 >= NT) || spad[lane + 32];
    bool p2 = (lane + 64 >= NT) || spad[lane + 64];

#pragma unroll
    for (int rr = 0; rr < 2; rr++) {
        float s0 = !p0 ? acc[rr][0] * scale : -INFINITY;
        float s1 = !p1 ? acc[rr][1] * scale : -INFINITY;
        float s2 = !p2 ? acc[rr][2] * scale : -INFINITY;

        uint32_t o0 = ford(s0), o1 = ford(s1), o2 = ford(s2);

        float topv[TOPM]; int topt[TOPM];
#pragma unroll
        for (int it = 0; it < TOPM; it++) {
            uint32_t loc = o0 > o1 ? o0 : o1;
            if (o2 > loc) loc = o2;
            uint32_t m = __reduce_max_sync(0xffffffffu, loc);
            topv[it] = finv(m);
            int t;
            unsigned b0 = __ballot_sync(0xffffffffu, o0 == m);
            if (b0) t = __ffs(b0) - 1;
            else {
                unsigned b1 = __ballot_sync(0xffffffffu, o1 == m);
                if (b1) t = 32 + __ffs(b1) - 1;
                else {
                    unsigned b2 = __ballot_sync(0xffffffffu, o2 == m);
                    t = 64 + __ffs(b2) - 1;
                }
            }
            topt[it] = t;
            if ((t & 31) == lane) {
                if (t < 32) o0 = 0u; else if (t < 64) o1 = 0u; else o2 = 0u;
            }
        }

        float outv = 0.f;
        float mx = topv[0];
        if (!(mx == -INFINITY)) {
            float e[TOPM]; float ws = 0.f;
#pragma unroll
            for (int i = 0; i < TOPM; i++) { e[i] = expf(topv[i] - mx); ws += e[i]; }
            float inv = 1.f / ws;
            const float* vb = g_v + (size_t)b * NT * CVD + h * DH + lane;
#pragma unroll
            for (int i = 0; i < TOPM; i++) outv += (e[i] * inv) * vb[(size_t)topt[i] * CVD];
        }
        g_aligned[(size_t)(row0 + rr) * CVD + h*DH + lane] = outv;
    }
}

// ---------------- bf16 split helpers ----------------
__device__ __forceinline__ void bf16_split_pack(float x0, float x1, uint32_t& hi, uint32_t& lo) {
    __nv_bfloat16 h0 = __float2bfloat16_rn(x0);
    __nv_bfloat16 h1 = __float2bfloat16_rn(x1);
    __nv_bfloat16 l0 = __float2bfloat16_rn(x0 - __bfloat162float(h0));
    __nv_bfloat16 l1 = __float2bfloat16_rn(x1 - __bfloat162float(h1));
    hi = (uint32_t)__bfloat16_as_ushort(h0) | ((uint32_t)__bfloat16_as_ushort(h1) << 16);
    lo = (uint32_t)__bfloat16_as_ushort(l0) | ((uint32_t)__bfloat16_as_ushort(l1) << 16);
}
__device__ __forceinline__ void mma16(float* c, const uint32_t* a, const uint32_t* b) {
    asm volatile("mma.sync.aligned.m16n8k16.row.col.f32.bf16.bf16.f32 "
        "{%0,%1,%2,%3}, {%4,%5,%6,%7}, {%8,%9}, {%0,%1,%2,%3};"
        : "+f"(c[0]), "+f"(c[1]), "+f"(c[2]), "+f"(c[3])
        : "r"(a[0]), "r"(a[1]), "r"(a[2]), "r"(a[3]), "r"(b[0]), "r"(b[1]));
}
__device__ __forceinline__ void ldsm4(uint32_t* r, uint32_t saddr) {
    asm volatile("ldmatrix.sync.aligned.m8n8.x4.shared.b16 {%0,%1,%2,%3}, [%4];"
        : "=r"(r[0]), "=r"(r[1]), "=r"(r[2]), "=r"(r[3]) : "r"(saddr));
}

// ---------------- split-bf16 GEMM, A and B fragments via ldmatrix ----------------
// A smem: row-major [m][k2], stride 12. B smem: n-major [n][k2], stride 12 (48B rows).
#define ASTRIDE 12
#define BSTRIDE 12
__global__ __launch_bounds__(256) void gemm_bf16s_kernel(const float* __restrict__ A,
                                                         const float* __restrict__ B,
                                                         const float* __restrict__ bias,
                                                         const float* __restrict__ res,
                                                         float* __restrict__ C,
                                                         int M, int N, int K, int mode) {
    __shared__ uint32_t AhS[2][128*ASTRIDE], AlS[2][128*ASTRIDE];
    __shared__ uint32_t BhS[2][64*BSTRIDE], BlS[2][64*BSTRIDE];

    int tid  = threadIdx.x;
    int lane = tid & 31, wid = tid >> 5;
    int warpM = wid & 3, warpN = wid >> 2;
    int g = lane >> 2, t4 = lane & 3;
    int m0 = blockIdx.y * 128, n0 = blockIdx.x * 64;
    int mbase = warpM * 32, nbase = warpN * 32;

    float c[2][4][4];
#pragma unroll
    for (int i = 0; i < 2; i++)
#pragma unroll
        for (int j = 0; j < 4; j++)
#pragma unroll
            for (int l = 0; l < 4; l++) c[i][j][l] = 0.f;

    int ar   = tid >> 1;
    int ha   = tid & 1;
    int aoff = ar * ASTRIDE + ha * 4;
    int bn   = tid & 63;
    int k2b  = (tid >> 6) * 2;
    const float* Aptr = A + (size_t)(m0 + ar) * K + 8*ha;
    const float* Bptr = B + (size_t)(2*k2b) * N + n0 + bn;

    int lrow = lane & 15;
    int lkof = (lane >> 4) * 4;
    // B ldmatrix addressing: matrix m = lane>>3; n-row = base + (m>>1)*8 + (lane&7); k-offset (m&1)*4
    int bm   = lane >> 3;
    int brow = ((bm >> 1) << 3) + (lane & 7);
    int bkof = (bm & 1) * 4;

    float4 av0, av1;
    float  b00, b01, b10, b11;
    av0 = *(const float4*)(Aptr);
    av1 = *(const float4*)(Aptr + 4);
    b00 = Bptr[0]; b01 = Bptr[N]; b10 = Bptr[2*N]; b11 = Bptr[3*N];

    {
        uint32_t h0,l0,h1,l1,h2,l2,h3,l3;
        bf16_split_pack(av0.x, av0.y, h0, l0);
        bf16_split_pack(av0.z, av0.w, h1, l1);
        bf16_split_pack(av1.x, av1.y, h2, l2);
        bf16_split_pack(av1.z, av1.w, h3, l3);
        *(uint4*)&AhS[0][aoff] = make_uint4(h0, h1, h2, h3);
        *(uint4*)&AlS[0][aoff] = make_uint4(l0, l1, l2, l3);
        uint32_t p0h, p0l, p1h, p1l;
        bf16_split_pack(b00, b01, p0h, p0l);
        bf16_split_pack(b10, b11, p1h, p1l);
        *(uint2*)&BhS[0][bn*BSTRIDE + k2b] = make_uint2(p0h, p1h);
        *(uint2*)&BlS[0][bn*BSTRIDE + k2b] = make_uint2(p0l, p1l);
    }

    int stage = 0;
    for (int k0 = 0; k0 < K; k0 += 16) {
        __syncthreads();
        bool more = (k0 + 16) < K;
        if (more) {
            av0 = *(const float4*)(Aptr + k0 + 16);
            av1 = *(const float4*)(Aptr + k0 + 20);
            const float* bp = Bptr + (size_t)(k0 + 16) * N;
            b00 = bp[0]; b01 = bp[N]; b10 = bp[2*N]; b11 = bp[3*N];
        }

        uint32_t ah[2][4], al[2][4], bh[4][2], blo[4][2];
#pragma unroll
        for (int mt = 0; mt < 2; mt++) {
            int r = mbase + mt*16 + lrow;
            uint32_t addrH = (uint32_t)__cvta_generic_to_shared(&AhS[stage][r*ASTRIDE + lkof]);
            uint32_t addrL = (uint32_t)__cvta_generic_to_shared(&AlS[stage][r*ASTRIDE + lkof]);
            ldsm4(ah[mt], addrH);
            ldsm4(al[mt], addrL);
        }
#pragma unroll
        for (int pair = 0; pair < 2; pair++) {
            int nrow = nbase + pair*16 + brow;
            uint32_t addrH = (uint32_t)__cvta_generic_to_shared(&BhS[stage][nrow*BSTRIDE + bkof]);
            uint32_t addrL = (uint32_t)__cvta_generic_to_shared(&BlS[stage][nrow*BSTRIDE + bkof]);
            uint32_t tH[4], tL[4];
            ldsm4(tH, addrH);
            ldsm4(tL, addrL);
            bh[pair*2  ][0] = tH[0]; bh[pair*2  ][1] = tH[1];
            bh[pair*2+1][0] = tH[2]; bh[pair*2+1][1] = tH[3];
            blo[pair*2  ][0] = tL[0]; blo[pair*2  ][1] = tL[1];
            blo[pair*2+1][0] = tL[2]; blo[pair*2+1][1] = tL[3];
        }
#pragma unroll
        for (int mt = 0; mt < 2; mt++)
#pragma unroll
            for (int nt = 0; nt < 4; nt++) {
                mma16(c[mt][nt], al[mt], bh[nt]);
                mma16(c[mt][nt], ah[mt], blo[nt]);
                mma16(c[mt][nt], ah[mt], bh[nt]);
            }

        if (more) {
            int ns = stage ^ 1;
            uint32_t h0,l0,h1,l1,h2,l2,h3,l3;
            bf16_split_pack(av0.x, av0.y, h0, l0);
            bf16_split_pack(av0.z, av0.w, h1, l1);
            bf16_split_pack(av1.x, av1.y, h2, l2);
            bf16_split_pack(av1.z, av1.w, h3, l3);
            *(uint4*)&AhS[ns][aoff] = make_uint4(h0, h1, h2, h3);
            *(uint4*)&AlS[ns][aoff] = make_uint4(l0, l1, l2, l3);
            uint32_t p0h, p0l, p1h, p1l;
            bf16_split_pack(b00, b01, p0h, p0l);
            bf16_split_pack(b10, b11, p1h, p1l);
            *(uint2*)&BhS[ns][bn*BSTRIDE + k2b] = make_uint2(p0h, p1h);
            *(uint2*)&BlS[ns][bn*BSTRIDE + k2b] = make_uint2(p0l, p1l);
        }
        stage ^= 1;
    }

    // epilogue: bias -> (optional l2norm) -> (optional gelu) -> (optional res) -> store
#pragma unroll
    for (int mt = 0; mt < 2; mt++)
#pragma unroll
        for (int nt = 0; nt < 4; nt++) {
            int col = n0 + nbase + nt*8 + t4*2;
            float b0v = bias[col], b1v = bias[col + 1];
            c[mt][nt][0] += b0v; c[mt][nt][1] += b1v;
            c[mt][nt][2] += b0v; c[mt][nt][3] += b1v;
        }

    if (mode == 2) {
#pragma unroll
        for (int mt = 0; mt < 2; mt++) {
            float ss0 = 0.f, ss1 = 0.f;
#pragma unroll
            for (int nt = 0; nt < 4; nt++) {
                ss0 += c[mt][nt][0]*c[mt][nt][0] + c[mt][nt][1]*c[mt][nt][1];
                ss1 += c[mt][nt][2]*c[mt][nt][2] + c[mt][nt][3]*c[mt][nt][3];
            }
            ss0 += __shfl_xor_sync(~0u, ss0, 1); ss0 += __shfl_xor_sync(~0u, ss0, 2);
            ss1 += __shfl_xor_sync(~0u, ss1, 1); ss1 += __shfl_xor_sync(~0u, ss1, 2);
            float i0 = 1.f / fmaxf(sqrtf(ss0), 1e-6f);
            float i1 = 1.f / fmaxf(sqrtf(ss1), 1e-6f);
#pragma unroll
            for (int nt = 0; nt < 4; nt++) {
                c[mt][nt][0] *= i0; c[mt][nt][1] *= i0;
                c[mt][nt][2] *= i1; c[mt][nt][3] *= i1;
            }
        }
    }

#pragma unroll
    for (int mt = 0; mt < 2; mt++)
#pragma unroll
        for (int nt = 0; nt < 4; nt++) {
            int col = n0 + nbase + nt*8 + t4*2;
            size_t r0 = (size_t)(m0 + mbase + mt*16 + g);
            size_t r1 = r0 + 8;
            float v0 = c[mt][nt][0], v1 = c[mt][nt][1];
            float v2 = c[mt][nt][2], v3 = c[mt][nt][3];
            if (mode == 1) {
                v0 = 0.5f*v0*(1.f + erff(v0*0.70710678118654752f));
                v1 = 0.5f*v1*(1.f + erff(v1*0.70710678118654752f));
                v2 = 0.5f*v2*(1.f + erff(v2*0.70710678118654752f));
                v3 = 0.5f*v3*(1.f + erff(v3*0.70710678118654752f));
            }
            if (res) {
                v0 += res[r0*N + col]; v1 += res[r0*N + col + 1];
                v2 += res[r1*N + col]; v3 += res[r1*N + col + 1];
            }
            *(float2*)&C[r0*N + col] = make_float2(v0, v1);
            *(float2*)&C[r1*N + col] = make_float2(v2, v3);
        }
}

// ---------------- launch ----------------
extern "C" void kernel_launch(void* const* d_in, const int* in_sizes, int n_in,
                              void* d_out, int out_size) {
    const float* vis   = (const float*)d_in[0];
    const float* text  = (const float*)d_in[1];
    const float* Wq    = (const float*)d_in[2];
    const float* bq    = (const float*)d_in[3];
    const float* Wk    = (const float*)d_in[4];
    const float* bk    = (const float*)d_in[5];
    const float* Wv    = (const float*)d_in[6];
    const float* bv    = (const float*)d_in[7];
    const float* Wo    = (const float*)d_in[8];
    const float* bo    = (const float*)d_in[9];
    const float* g1    = (const float*)d_in[10];
    const float* b1    = (const float*)d_in[11];
    const float* g2    = (const float*)d_in[12];
    const float* b2    = (const float*)d_in[13];
    const float* Wf1   = (const float*)d_in[14];
    const float* bf1   = (const float*)d_in[15];
    const float* Wf2   = (const float*)d_in[16];
    const float* bf2   = (const float*)d_in[17];
    const float* ls    = (const float*)d_in[18];
    const float* alpha = (const float*)d_in[19];
    float* out = (float*)d_out;

    float *px, *pq, *paligned, *pproj, *py2, *phdn;
    cudaGetSymbolAddress((void**)&px,       g_x);
    cudaGetSymbolAddress((void**)&pq,       g_q);
    cudaGetSymbolAddress((void**)&paligned, g_aligned);
    cudaGetSymbolAddress((void**)&pproj,    g_proj);
    cudaGetSymbolAddress((void**)&py2,      g_y2);
    cudaGetSymbolAddress((void**)&phdn,     g_hdn);

    // fork kv onto a side stream so it overlaps ln1 + q-GEMM (capture-legal fork/join)
    cudaStream_t s2;
    cudaEvent_t evA, evB;
    cudaStreamCreateWithFlags(&s2, cudaStreamNonBlocking);
    cudaEventCreateWithFlags(&evA, cudaEventDisableTiming);
    cudaEventCreateWithFlags(&evB, cudaEventDisableTiming);

    cudaEventRecord(evA, 0);
    cudaStreamWaitEvent(s2, evA, 0);
    kv_kernel<<<NB*NT, 256, 0, s2>>>(text, Wk, bk, Wv, bv);
    cudaEventRecord(evB, s2);

    ln1_kernel<<<ROWS/8, 256>>>(vis, g1, b1);
    gemm_bf16s_kernel<<<dim3(CVD/64, ROWS/128), 256>>>(px, Wq, bq, nullptr, pq, ROWS, CVD, CVD, 2);

    cudaStreamWaitEvent(0, evB, 0);
    attn_kernel<<<ROWS/2, 256>>>(ls);
    gemm_bf16s_kernel<<<dim3(CVD/64, ROWS/128), 256>>>(paligned, Wo, bo, nullptr, pproj, ROWS, CVD, CVD, 0);
    ln2res_kernel<<<ROWS/8, 256>>>(g2, b2, alpha);
    gemm_bf16s_kernel<<<dim3(4*CVD/64, ROWS/128), 256>>>(py2, Wf1, bf1, nullptr, phdn, ROWS, 4*CVD, CVD, 1);
    gemm_bf16s_kernel<<<dim3(CVD/64, ROWS/128), 256>>>(phdn, Wf2, bf2, py2, out, ROWS, CVD, 4*CVD, 0);
}